// round 16
// baseline (speedup 1.0000x reference)
#include <cuda_runtime.h>
#include <cuda_fp16.h>
#include <math.h>
#include <stdint.h>

// ---------------- problem constants ----------------
#define RTOT   32768          // B*N = 32*1024
#define CIN    384
#define HID    1024
#define NRES   20

// output layout (floats)
#define OFF_LOGITS 0
#define OFF_SEQ0   655360
#define OFF_PRED   688128
#define OFF_FINAL  2064384
#define OFF_M14    5701632
#define OFF_M37    6160384

// ---------------- scratch (no cudaMalloc allowed) ----------------
__device__ __align__(256) __half g_xn_hi[(size_t)RTOT * CIN];
__device__ __align__(256) __half g_xn_lo[(size_t)RTOT * CIN];
__device__ __align__(256) __half g_h1_hi[(size_t)RTOT * HID];
__device__ __align__(256) __half g_h1_lo[(size_t)RTOT * HID];
__device__ __align__(256) __half g_wt1_hi[(size_t)HID * CIN];
__device__ __align__(256) __half g_wt1_lo[(size_t)HID * CIN];
__device__ __align__(256) __half g_wt2_hi[(size_t)HID * HID];
__device__ __align__(256) __half g_wt2_lo[(size_t)HID * HID];
__device__ __align__(256) float  g_part[(size_t)4 * RTOT * NRES];   // per-n-tile logit partials
__device__ int g_mcnt[256];   // per-m-tile completion counters (GEMM1 -> GEMM2)

__device__ __forceinline__ void mma16(float c[4], const uint32_t a[4], const uint32_t b[2]) {
    asm volatile("mma.sync.aligned.m16n8k16.row.col.f32.f16.f16.f32 "
        "{%0,%1,%2,%3}, {%4,%5,%6,%7}, {%8,%9}, {%0,%1,%2,%3};"
        : "+f"(c[0]), "+f"(c[1]), "+f"(c[2]), "+f"(c[3])
        : "r"(a[0]), "r"(a[1]), "r"(a[2]), "r"(a[3]), "r"(b[0]), "r"(b[1]));
}

__device__ __forceinline__ void ldsm4(uint32_t r[4], uint32_t addr) {
    asm volatile("ldmatrix.sync.aligned.m8n8.x4.shared.b16 {%0,%1,%2,%3}, [%4];"
        : "=r"(r[0]), "=r"(r[1]), "=r"(r[2]), "=r"(r[3]) : "r"(addr));
}

__device__ __forceinline__ uint32_t smem_u32(const void* p) {
    uint32_t a;
    asm("{ .reg .u64 t; cvta.to.shared.u64 t, %1; cvt.u32.u64 %0, t; }" : "=r"(a) : "l"(p));
    return a;
}

#define CP16(dst, src) \
    asm volatile("cp.async.cg.shared.global [%0], [%1], 16;" :: "r"(dst), "l"(src))
#define CP_COMMIT() asm volatile("cp.async.commit_group;" ::: "memory")
#define CP_WAIT(n)  asm volatile("cp.async.wait_group %0;" :: "n"(n) : "memory")

// ---------------- LayerNorm -> split fp16 hi/lo (+ counter reset) ----------------
__global__ __launch_bounds__(512) void ln_kernel(
    const float* __restrict__ act,
    const float* __restrict__ gamma,
    const float* __restrict__ beta,
    __half* __restrict__ out_hi,
    __half* __restrict__ out_lo)
{
    if (blockIdx.x == 0 && threadIdx.x < 256) g_mcnt[threadIdx.x] = 0;

    int row  = blockIdx.x * 16 + (threadIdx.x >> 5);
    int lane = threadIdx.x & 31;
    const float* x = act + (size_t)row * CIN;

    float v[12];
    float sum = 0.f;
#pragma unroll
    for (int i = 0; i < 12; i++) { v[i] = x[lane + i * 32]; sum += v[i]; }
#pragma unroll
    for (int o = 16; o; o >>= 1) sum += __shfl_xor_sync(0xffffffffu, sum, o);
    float mu = sum * (1.f / CIN);

    float vs = 0.f;
#pragma unroll
    for (int i = 0; i < 12; i++) { float d = v[i] - mu; vs += d * d; }
#pragma unroll
    for (int o = 16; o; o >>= 1) vs += __shfl_xor_sync(0xffffffffu, vs, o);
    float rstd = rsqrtf(vs * (1.f / CIN) + 1e-5f);

    __half* oh = out_hi + (size_t)row * CIN;
    __half* ol = out_lo + (size_t)row * CIN;
#pragma unroll
    for (int i = 0; i < 12; i++) {
        int c = lane + i * 32;
        float y = (v[i] - mu) * rstd * gamma[c] + beta[c];
        __half hi = __float2half_rn(y);
        oh[c] = hi;
        ol[c] = __float2half_rn(y - __half2float(hi));
    }
}

// ---------------- coalesced transpose + fp16 split: W[K,N] -> T[N,K] hi/lo ----------------
__global__ __launch_bounds__(256) void tsplit_kernel(
    const float* __restrict__ W, __half* __restrict__ Th, __half* __restrict__ Tl,
    int Krows, int Ncols)
{
    __shared__ float t[32][33];
    const int tx = threadIdx.x;    // 0..31
    const int ty = threadIdx.y;    // 0..7
    const int n0 = blockIdx.x * 32;
    const int k0 = blockIdx.y * 32;

#pragma unroll
    for (int j = ty; j < 32; j += 8)
        t[j][tx] = W[(size_t)(k0 + j) * Ncols + n0 + tx];
    __syncthreads();

#pragma unroll
    for (int j = ty; j < 32; j += 8) {
        float v = t[tx][j];
        __half hi = __float2half_rn(v);
        size_t o = (size_t)(n0 + j) * Krows + k0 + tx;
        Th[o] = hi;
        Tl[o] = __float2half_rn(v - __half2float(hi));
    }
}

// ---------------- fused fp16x3 GEMM1+GEMM2, producer-consumer over m-tiles ----------------
// bids 0..1023: GEMM1 (K=384) -> h1 hi/lo, signal g_mcnt[m]
// bids 1024..2047: GEMM2 (K=1024), wait g_mcnt[m]==4, fused logit-partial epilogue
// block tile 128(M) x 256(N) x 32(K), 16 warps (4M x 4N), warp tile 32x64
#define SRB    176                      // bytes per smem row (11x16B, conflict-free)
#define A_ARRB (128 * SRB)              // 22528 B
#define B_ARRB (256 * SRB)              // 45056 B
#define ST_A   0
#define ST_B   A_ARRB
#define STAGEB (A_ARRB + B_ARRB)        // 67584 B
#define NSTAGE 3
#define LO_OFF 32                       // byte offset of lo half within a k16 slab

__global__ __launch_bounds__(512, 1) void fused_gemm_kernel(
    const __half* __restrict__ xnh, const __half* __restrict__ xnl,
    const __half* __restrict__ wt1h, const __half* __restrict__ wt1l,
    const __half* __restrict__ wt2h, const __half* __restrict__ wt2l,
    const float* __restrict__ b1,  const float* __restrict__ b2,
    __half* __restrict__ h1h, __half* __restrict__ h1l,
    const float* __restrict__ w3,
    float* __restrict__ gpart)
{
    extern __shared__ char smem[];

    const bool role2 = blockIdx.x >= 1024;
    const int  bid   = role2 ? (blockIdx.x - 1024) : blockIdx.x;
    const int  midx  = bid >> 2;
    const int  m0    = midx * 128;
    const int  n0    = (bid & 3) * 256;
    const int  K     = role2 ? HID : CIN;
    const int  KT    = K / 32;

    const __half* Ah = role2 ? h1h : xnh;
    const __half* Al = role2 ? h1l : xnl;
    const __half* Bh = role2 ? wt2h : wt1h;
    const __half* Bl = role2 ? wt2l : wt1l;
    const float* bias = role2 ? b2 : b1;

    const int tid   = threadIdx.x;
    const int wid   = tid >> 5;
    const int lane  = tid & 31;
    const int warpM = wid & 3;
    const int warpN = wid >> 2;
    const int gr    = lane >> 2;
    const int tc    = lane & 3;

    const int row = tid >> 2;
    const int p0  = tid & 3;
    const int hl  = (p0 >> 1) & 1;
    const int seg = p0 & 1;
    const __half* gA  = (hl ? Al : Ah) + (size_t)(m0 + row) * K + seg * 8;
    const __half* gB0 = (hl ? Bl : Bh) + (size_t)(n0 + row) * K + seg * 8;
    const __half* gB1 = (hl ? Bl : Bh) + (size_t)(n0 + row + 128) * K + seg * 8;

    const uint32_t sbase = smem_u32(smem);
    const uint32_t dpart = (uint32_t)(hl * 32 + seg * 16);
    const uint32_t dstA  = (uint32_t)(row * SRB) + dpart;
    const uint32_t dstB0 = (uint32_t)(row * SRB) + dpart;
    const uint32_t dstB1 = (uint32_t)((row + 128) * SRB) + dpart;

    const uint32_t aLane = (uint32_t)((warpM * 32 + (lane & 15)) * SRB + (lane >> 4) * 16);
    const uint32_t bLane = (uint32_t)((warpN * 64 + (lane & 7) + ((lane >> 4) & 1) * 8) * SRB
                                      + ((lane >> 3) & 1) * 16);

    // GEMM2: wait for this m-tile's 4 GEMM1 producers
    if (role2) {
        if (tid == 0) {
            while (atomicAdd(&g_mcnt[midx], 0) < 4) { __nanosleep(256); }
        }
        __syncthreads();
        __threadfence();
    }

    float acc[2][8][4];
#pragma unroll
    for (int i = 0; i < 2; i++)
#pragma unroll
        for (int j = 0; j < 8; j++)
#pragma unroll
            for (int q = 0; q < 4; q++) acc[i][j][q] = 0.f;

#define PREFETCH(kt_, s_) do { \
        const int _kg = (kt_) * 32; \
        const uint32_t _db = sbase + (uint32_t)(s_) * STAGEB; \
        CP16(_db + ST_A + dstA,       gA  + _kg); \
        CP16(_db + ST_A + dstA + 64,  gA  + _kg + 16); \
        CP16(_db + ST_B + dstB0,      gB0 + _kg); \
        CP16(_db + ST_B + dstB0 + 64, gB0 + _kg + 16); \
        CP16(_db + ST_B + dstB1,      gB1 + _kg); \
        CP16(_db + ST_B + dstB1 + 64, gB1 + _kg + 16); \
        CP_COMMIT(); \
    } while (0)

    PREFETCH(0, 0);
    PREFETCH(1, 1);

    int s_cur = 0;
    int s_pf  = 2;
    for (int kt = 0; kt < KT; ++kt) {
        if (kt < KT - 1) { CP_WAIT(1); }
        else             { CP_WAIT(0); }
        __syncthreads();
        if (kt + 2 < KT) {
            PREFETCH(kt + 2, s_pf);
        }

        const uint32_t stage = sbase + (uint32_t)s_cur * STAGEB;

#pragma unroll
        for (int j = 0; j < 2; j++) {
            const uint32_t aHi = stage + ST_A + aLane + j * 64;
            const uint32_t bHi = stage + ST_B + bLane + j * 64;

            uint32_t ah[2][4], al[2][4], bh[4][4], bl[4][4];
#pragma unroll
            for (int ms = 0; ms < 2; ms++) {
                ldsm4(ah[ms], aHi + ms * (16 * SRB));
                ldsm4(al[ms], aHi + ms * (16 * SRB) + LO_OFF);
            }
#pragma unroll
            for (int p = 0; p < 4; p++) {
                ldsm4(bh[p], bHi + p * (16 * SRB));
                ldsm4(bl[p], bHi + p * (16 * SRB) + LO_OFF);
            }
#pragma unroll
            for (int ms = 0; ms < 2; ms++)
#pragma unroll
                for (int p = 0; p < 4; p++) {
                    mma16(acc[ms][2 * p],     ah[ms], &bh[p][0]);
                    mma16(acc[ms][2 * p + 1], ah[ms], &bh[p][2]);
                }
#pragma unroll
            for (int ms = 0; ms < 2; ms++)
#pragma unroll
                for (int p = 0; p < 4; p++) {
                    mma16(acc[ms][2 * p],     ah[ms], &bl[p][0]);
                    mma16(acc[ms][2 * p + 1], ah[ms], &bl[p][2]);
                }
#pragma unroll
            for (int ms = 0; ms < 2; ms++)
#pragma unroll
                for (int p = 0; p < 4; p++) {
                    mma16(acc[ms][2 * p],     al[ms], &bh[p][0]);
                    mma16(acc[ms][2 * p + 1], al[ms], &bh[p][2]);
                }
        }
        s_cur = (s_cur == 2) ? 0 : s_cur + 1;
        s_pf  = (s_pf == 2) ? 0 : s_pf + 1;
    }
#undef PREFETCH

    // bias + relu in place
    const int mwb = m0 + warpM * 32;
    const int nwb = n0 + warpN * 64;
#pragma unroll
    for (int ms = 0; ms < 2; ms++)
#pragma unroll
        for (int ns = 0; ns < 8; ns++) {
            int c = nwb + ns * 8 + 2 * tc;
            float bz0 = bias[c], bz1 = bias[c + 1];
            acc[ms][ns][0] = fmaxf(acc[ms][ns][0] + bz0, 0.f);
            acc[ms][ns][1] = fmaxf(acc[ms][ns][1] + bz1, 0.f);
            acc[ms][ns][2] = fmaxf(acc[ms][ns][2] + bz0, 0.f);
            acc[ms][ns][3] = fmaxf(acc[ms][ns][3] + bz1, 0.f);
        }

    if (!role2) {
        // GEMM1 epilogue: fp16 hi/lo split stores, then signal
#pragma unroll
        for (int ms = 0; ms < 2; ms++) {
            int r0 = mwb + ms * 16 + gr;
            int r1 = r0 + 8;
#pragma unroll
            for (int ns = 0; ns < 8; ns++) {
                int c = nwb + ns * 8 + 2 * tc;
                float v0 = acc[ms][ns][0], v1 = acc[ms][ns][1];
                float v2 = acc[ms][ns][2], v3 = acc[ms][ns][3];
                __half h0 = __float2half_rn(v0), h1 = __float2half_rn(v1);
                __half h2 = __float2half_rn(v2), h3 = __float2half_rn(v3);
                __half l0 = __float2half_rn(v0 - __half2float(h0));
                __half l1 = __float2half_rn(v1 - __half2float(h1));
                __half l2 = __float2half_rn(v2 - __half2float(h2));
                __half l3 = __float2half_rn(v3 - __half2float(h3));
                *(__half2*)(h1h + (size_t)r0 * HID + c) = __halves2half2(h0, h1);
                *(__half2*)(h1h + (size_t)r1 * HID + c) = __halves2half2(h2, h3);
                *(__half2*)(h1l + (size_t)r0 * HID + c) = __halves2half2(l0, l1);
                *(__half2*)(h1l + (size_t)r1 * HID + c) = __halves2half2(l2, l3);
            }
        }
        __threadfence();
        __syncthreads();
        if (tid == 0) atomicAdd(&g_mcnt[midx], 1);
    } else {
        // GEMM2 epilogue: fused logit partials
        __syncthreads();
        float* w3s  = (float*)smem;                      // [256][20]
        float* slab = (float*)(smem + 256 * NRES * 4);   // [4 warpN][128][20]
        for (int i = tid; i < 256 * NRES; i += 512) {
            int col = i / NRES, c = i - col * NRES;
            w3s[i] = w3[(size_t)(n0 + col) * NRES + c];
        }
        __syncthreads();

#pragma unroll
        for (int cc = 0; cc < 5; cc++) {
            float pl[4][4];
#pragma unroll
            for (int ri = 0; ri < 4; ri++)
#pragma unroll
                for (int q = 0; q < 4; q++) pl[ri][q] = 0.f;
#pragma unroll
            for (int ns = 0; ns < 8; ns++) {
                int colb = warpN * 64 + ns * 8 + 2 * tc;
                float4 w0 = *(float4*)&w3s[colb * NRES + cc * 4];
                float4 w1 = *(float4*)&w3s[(colb + 1) * NRES + cc * 4];
#pragma unroll
                for (int ms = 0; ms < 2; ms++)
#pragma unroll
                    for (int q = 0; q < 4; q++) {
                        float v = acc[ms][ns][q];
                        const float4 wv = (q & 1) ? w1 : w0;
                        int ri = ms * 2 + (q >> 1);
                        pl[ri][0] = fmaf(v, wv.x, pl[ri][0]);
                        pl[ri][1] = fmaf(v, wv.y, pl[ri][1]);
                        pl[ri][2] = fmaf(v, wv.z, pl[ri][2]);
                        pl[ri][3] = fmaf(v, wv.w, pl[ri][3]);
                    }
            }
#pragma unroll
            for (int o = 1; o <= 2; o <<= 1)
#pragma unroll
                for (int ri = 0; ri < 4; ri++)
#pragma unroll
                    for (int q = 0; q < 4; q++)
                        pl[ri][q] += __shfl_xor_sync(0xffffffffu, pl[ri][q], o);
            if (tc == 0) {
#pragma unroll
                for (int ri = 0; ri < 4; ri++) {
                    int rloc = warpM * 32 + (ri >> 1) * 16 + (ri & 1) * 8 + gr;
                    float4 st = make_float4(pl[ri][0], pl[ri][1], pl[ri][2], pl[ri][3]);
                    *(float4*)&slab[(warpN * 128 + rloc) * NRES + cc * 4] = st;
                }
            }
        }
        __syncthreads();
        for (int i = tid; i < 128 * NRES; i += 512) {
            float s = slab[i] + slab[128 * NRES + i]
                    + slab[2 * 128 * NRES + i] + slab[3 * 128 * NRES + i];
            int rloc = i / NRES, c = i - rloc * NRES;
            gpart[((size_t)(bid & 3) * RTOT + (m0 + rloc)) * NRES + c] = s;
        }
    }
}

// ---------------- fused head + geometry: 128 thr/block, warp-staged coalesced writes ----------------
__global__ __launch_bounds__(128) void head_geom_kernel(
    const float* __restrict__ gpart,
    const float* __restrict__ b3,
    const int* __restrict__ fixed_mask,
    const int* __restrict__ seq_t,
    const float* __restrict__ angles,
    const float* __restrict__ rigids,
    const int* __restrict__ residx,
    const float* __restrict__ default_frames,
    const int* __restrict__ group_idx,
    const float* __restrict__ atom14_mask,
    const float* __restrict__ atom37_mask,
    const float* __restrict__ lit_positions,
    float* __restrict__ out_logits,
    float* __restrict__ out_seq0f,
    float* __restrict__ out_pred,
    float* __restrict__ out_final,
    float* __restrict__ out_m14,
    float* __restrict__ out_m37)
{
    __shared__ float slab[4][32 * 42];
    __shared__ int   s_sh[4][32];

    const int tid  = threadIdx.x;
    const int wid  = tid >> 5;
    const int lane = tid & 31;
    const int r    = blockIdx.x * 128 + tid;
    const int rwb  = blockIdx.x * 128 + wid * 32;

    float* sl = slab[wid];

    float lg[NRES];
#pragma unroll
    for (int c = 0; c < NRES; c++) lg[c] = b3[c];
#pragma unroll
    for (int nt = 0; nt < 4; nt++) {
        const float* p = gpart + ((size_t)nt * RTOT + r) * NRES;
#pragma unroll
        for (int c = 0; c < NRES; c += 4) {
            float4 v = *(const float4*)(p + c);
            lg[c + 0] += v.x; lg[c + 1] += v.y; lg[c + 2] += v.z; lg[c + 3] += v.w;
        }
    }
    int best = 0; float bv = -INFINITY;
#pragma unroll
    for (int c = 0; c < NRES; c++) {
        sl[lane * NRES + c] = lg[c];
        if (lg[c] > bv) { bv = lg[c]; best = c; }
    }
    int s = fixed_mask[r] ? seq_t[r] : best;
    s_sh[wid][lane] = s;
    out_seq0f[r] = (float)s;
    __syncwarp();
    for (int f = lane; f < 32 * NRES; f += 32)
        out_logits[(size_t)rwb * NRES + f] = sl[f];
    __syncwarp();

    float q0 = rigids[r * 7 + 0], q1 = rigids[r * 7 + 1];
    float q2 = rigids[r * 7 + 2], q3 = rigids[r * 7 + 3];
    float tb0 = rigids[r * 7 + 4], tb1 = rigids[r * 7 + 5], tb2 = rigids[r * 7 + 6];
    float inv = rsqrtf(q0 * q0 + q1 * q1 + q2 * q2 + q3 * q3 + 1e-8f);
    float w = q0 * inv, x = q1 * inv, y = q2 * inv, z = q3 * inv;
    float rb[9];
    rb[0] = 1.f - 2.f * (y * y + z * z); rb[1] = 2.f * (x * y - w * z); rb[2] = 2.f * (x * z + w * y);
    rb[3] = 2.f * (x * y + w * z); rb[4] = 1.f - 2.f * (x * x + z * z); rb[5] = 2.f * (y * z - w * x);
    rb[6] = 2.f * (x * z - w * y); rb[7] = 2.f * (y * z + w * x); rb[8] = 1.f - 2.f * (x * x + y * y);

    float G[8][12];
    float chain_r[9], chain_t[3];

    for (int g = 0; g < 8; g++) {
        const float* df = default_frames + ((size_t)s * 8 + g) * 16;
        float dr[9], dt[3];
#pragma unroll
        for (int i = 0; i < 3; i++) {
            dr[i * 3 + 0] = df[i * 4 + 0];
            dr[i * 3 + 1] = df[i * 4 + 1];
            dr[i * 3 + 2] = df[i * 4 + 2];
            dt[i] = df[i * 4 + 3];
        }
        float sn, cs;
        if (g == 0) { sn = 0.f; cs = 1.f; }
        else { sn = angles[r * 14 + (g - 1) * 2 + 0]; cs = angles[r * 14 + (g - 1) * 2 + 1]; }

        float fr[9], ft[3];
#pragma unroll
        for (int i = 0; i < 3; i++) {
            fr[i * 3 + 0] = dr[i * 3 + 0];
            fr[i * 3 + 1] = dr[i * 3 + 1] * cs + dr[i * 3 + 2] * sn;
            fr[i * 3 + 2] = -dr[i * 3 + 1] * sn + dr[i * 3 + 2] * cs;
            ft[i] = dt[i];
        }

        float fo[9], to[3];
        if (g <= 4) {
#pragma unroll
            for (int i = 0; i < 9; i++) fo[i] = fr[i];
#pragma unroll
            for (int i = 0; i < 3; i++) to[i] = ft[i];
            if (g == 4) {
#pragma unroll
                for (int i = 0; i < 9; i++) chain_r[i] = fr[i];
#pragma unroll
                for (int i = 0; i < 3; i++) chain_t[i] = ft[i];
            }
        } else {
            float nr[9], nt[3];
#pragma unroll
            for (int i = 0; i < 3; i++) {
#pragma unroll
                for (int j = 0; j < 3; j++) {
                    nr[i * 3 + j] = chain_r[i * 3 + 0] * fr[0 * 3 + j]
                                  + chain_r[i * 3 + 1] * fr[1 * 3 + j]
                                  + chain_r[i * 3 + 2] * fr[2 * 3 + j];
                }
                nt[i] = chain_r[i * 3 + 0] * ft[0] + chain_r[i * 3 + 1] * ft[1]
                      + chain_r[i * 3 + 2] * ft[2] + chain_t[i];
            }
#pragma unroll
            for (int i = 0; i < 9; i++) { chain_r[i] = nr[i]; fo[i] = nr[i]; }
#pragma unroll
            for (int i = 0; i < 3; i++) { chain_t[i] = nt[i]; to[i] = nt[i]; }
        }

#pragma unroll
        for (int i = 0; i < 3; i++) {
#pragma unroll
            for (int j = 0; j < 3; j++) {
                G[g][i * 3 + j] = rb[i * 3 + 0] * fo[0 * 3 + j]
                                + rb[i * 3 + 1] * fo[1 * 3 + j]
                                + rb[i * 3 + 2] * fo[2 * 3 + j];
            }
        }
        G[g][9]  = rb[0] * to[0] + rb[1] * to[1] + rb[2] * to[2] + tb0;
        G[g][10] = rb[3] * to[0] + rb[4] * to[1] + rb[5] * to[2] + tb1;
        G[g][11] = rb[6] * to[0] + rb[7] * to[1] + rb[8] * to[2] + tb2;
    }

#pragma unroll
    for (int a = 0; a < 14; a++) {
        int gi = group_idx[s * 14 + a];
        const float* Gp = G[gi];
        float lx = lit_positions[((size_t)s * 14 + a) * 3 + 0];
        float ly = lit_positions[((size_t)s * 14 + a) * 3 + 1];
        float lz = lit_positions[((size_t)s * 14 + a) * 3 + 2];
        float m = atom14_mask[s * 14 + a];
        sl[lane * 42 + a * 3 + 0] = (Gp[0] * lx + Gp[1] * ly + Gp[2] * lz + Gp[9])  * m;
        sl[lane * 42 + a * 3 + 1] = (Gp[3] * lx + Gp[4] * ly + Gp[5] * lz + Gp[10]) * m;
        sl[lane * 42 + a * 3 + 2] = (Gp[6] * lx + Gp[7] * ly + Gp[8] * lz + Gp[11]) * m;
    }
    __syncwarp();

    for (int f = lane; f < 32 * 42; f += 32)
        out_pred[(size_t)rwb * 42 + f] = sl[f];

    for (int f = lane; f < 32 * 14; f += 32) {
        int rr = f / 14, a = f - rr * 14;
        out_m14[(size_t)rwb * 14 + f] = atom14_mask[s_sh[wid][rr] * 14 + a];
    }

    for (int f = lane; f < 32 * 37; f += 32) {
        int rr = f / 37, j = f - rr * 37;
        out_m37[(size_t)rwb * 37 + f] = atom37_mask[s_sh[wid][rr] * 37 + j];
    }

    for (int f = lane; f < 32 * 111; f += 32) {
        int rr = f / 111;
        int rem = f - rr * 111;
        int j = rem / 3, q = rem - j * 3;
        int a = residx[(size_t)(rwb + rr) * 37 + j];
        out_final[(size_t)rwb * 111 + f] = sl[rr * 42 + a * 3 + q];
    }
}

// ---------------- launcher ----------------
extern "C" void kernel_launch(void* const* d_in, const int* in_sizes, int n_in,
                              void* d_out, int out_size)
{
    const float* act        = (const float*)d_in[0];
    const float* angles     = (const float*)d_in[1];
    const float* rigids     = (const float*)d_in[2];
    const int*   fixed_mask = (const int*)d_in[3];
    const int*   seq_t      = (const int*)d_in[4];
    const int*   residx     = (const int*)d_in[5];
    const float* ln_g       = (const float*)d_in[6];
    const float* ln_b       = (const float*)d_in[7];
    const float* w1         = (const float*)d_in[8];
    const float* b1         = (const float*)d_in[9];
    const float* w2         = (const float*)d_in[10];
    const float* b2         = (const float*)d_in[11];
    const float* w3         = (const float*)d_in[12];
    const float* b3         = (const float*)d_in[13];
    const float* dframes    = (const float*)d_in[14];
    const int*   group_idx  = (const int*)d_in[15];
    const float* a14_mask   = (const float*)d_in[16];
    const float* a37_mask   = (const float*)d_in[17];
    const float* lit        = (const float*)d_in[18];

    float* out = (float*)d_out;
    float* out_logits = out + OFF_LOGITS;
    float* out_seq0   = out + OFF_SEQ0;
    float* out_pred   = out + OFF_PRED;
    float* out_final  = out + OFF_FINAL;
    float* out_m14    = out + OFF_M14;
    float* out_m37    = out + OFF_M37;

    __half *xnh, *xnl, *h1h, *h1l, *wt1h, *wt1l, *wt2h, *wt2l;
    float *gpart;
    cudaGetSymbolAddress((void**)&xnh, g_xn_hi);
    cudaGetSymbolAddress((void**)&xnl, g_xn_lo);
    cudaGetSymbolAddress((void**)&h1h, g_h1_hi);
    cudaGetSymbolAddress((void**)&h1l, g_h1_lo);
    cudaGetSymbolAddress((void**)&wt1h, g_wt1_hi);
    cudaGetSymbolAddress((void**)&wt1l, g_wt1_lo);
    cudaGetSymbolAddress((void**)&wt2h, g_wt2_hi);
    cudaGetSymbolAddress((void**)&wt2l, g_wt2_lo);
    cudaGetSymbolAddress((void**)&gpart, g_part);

    const int GEMM_SMEM = NSTAGE * STAGEB;   // 202752 B -> 1 CTA, 16 warps/SM
    cudaFuncSetAttribute(fused_gemm_kernel,
                         cudaFuncAttributeMaxDynamicSharedMemorySize, GEMM_SMEM);

    // 1. LayerNorm (+ counter reset) with fp16 split output
    ln_kernel<<<RTOT / 16, 512>>>(act, ln_g, ln_b, xnh, xnl);

    // 2. weight prep: coalesced transpose + fp16 split
    {
        dim3 blk(32, 8);
        dim3 g1(HID / 32, CIN / 32);
        tsplit_kernel<<<g1, blk>>>(w1, wt1h, wt1l, CIN, HID);
        dim3 g2(HID / 32, HID / 32);
        tsplit_kernel<<<g2, blk>>>(w2, wt2h, wt2l, HID, HID);
    }

    // 3. fused GEMM1 + GEMM2 (producer-consumer over m-tiles)
    fused_gemm_kernel<<<2048, 512, GEMM_SMEM>>>(
        xnh, xnl, wt1h, wt1l, wt2h, wt2l, b1, b2, h1h, h1l, w3, gpart);

    // 4. fused head + geometry (coalesced staged writes)
    head_geom_kernel<<<RTOT / 128, 128>>>(gpart, b3, fixed_mask, seq_t,
                                          angles, rigids, residx, dframes, group_idx,
                                          a14_mask, a37_mask, lit,
                                          out_logits, out_seq0,
                                          out_pred, out_final, out_m14, out_m37);
}

// round 17
// speedup vs baseline: 1.0233x; 1.0233x over previous
#include <cuda_runtime.h>
#include <cuda_fp16.h>
#include <math.h>
#include <stdint.h>

// ---------------- problem constants ----------------
#define RTOT   32768          // B*N = 32*1024
#define CIN    384
#define HID    1024
#define NRES   20

// output layout (floats)
#define OFF_LOGITS 0
#define OFF_SEQ0   655360
#define OFF_PRED   688128
#define OFF_FINAL  2064384
#define OFF_M14    5701632
#define OFF_M37    6160384

// ---------------- scratch (no cudaMalloc allowed) ----------------
__device__ __align__(256) __half g_xn_hi[(size_t)RTOT * CIN];
__device__ __align__(256) __half g_xn_lo[(size_t)RTOT * CIN];
__device__ __align__(256) __half g_h1_hi[(size_t)RTOT * HID];
__device__ __align__(256) __half g_h1_lo[(size_t)RTOT * HID];
__device__ __align__(256) __half g_wt1_hi[(size_t)HID * CIN];
__device__ __align__(256) __half g_wt1_lo[(size_t)HID * CIN];
__device__ __align__(256) __half g_wt2_hi[(size_t)HID * HID];
__device__ __align__(256) __half g_wt2_lo[(size_t)HID * HID];
__device__ __align__(256) float  g_part[(size_t)4 * RTOT * NRES];   // per-n-tile logit partials

__device__ __forceinline__ void mma16(float c[4], const uint32_t a[4], const uint32_t b[2]) {
    asm volatile("mma.sync.aligned.m16n8k16.row.col.f32.f16.f16.f32 "
        "{%0,%1,%2,%3}, {%4,%5,%6,%7}, {%8,%9}, {%0,%1,%2,%3};"
        : "+f"(c[0]), "+f"(c[1]), "+f"(c[2]), "+f"(c[3])
        : "r"(a[0]), "r"(a[1]), "r"(a[2]), "r"(a[3]), "r"(b[0]), "r"(b[1]));
}

__device__ __forceinline__ void ldsm4(uint32_t r[4], uint32_t addr) {
    asm volatile("ldmatrix.sync.aligned.m8n8.x4.shared.b16 {%0,%1,%2,%3}, [%4];"
        : "=r"(r[0]), "=r"(r[1]), "=r"(r[2]), "=r"(r[3]) : "r"(addr));
}

__device__ __forceinline__ uint32_t smem_u32(const void* p) {
    uint32_t a;
    asm("{ .reg .u64 t; cvta.to.shared.u64 t, %1; cvt.u32.u64 %0, t; }" : "=r"(a) : "l"(p));
    return a;
}

#define CP16(dst, src) \
    asm volatile("cp.async.cg.shared.global [%0], [%1], 16;" :: "r"(dst), "l"(src))
#define CP_COMMIT() asm volatile("cp.async.commit_group;" ::: "memory")
#define CP_WAIT(n)  asm volatile("cp.async.wait_group %0;" :: "n"(n) : "memory")

// ---------------- combined prep: LN split + both weight transposes ----------------
// blocks [0, 4096): LN, 8 rows each (256 thr = 8 warps)
// blocks [4096, 4480): w1 transpose-split, 32x32 tiles (12 x 32 grid flattened)
// blocks [4480, 5504): w2 transpose-split, 32x32 tiles (32 x 32 grid flattened)
#define LN_BLOCKS 4096
#define W1_BLOCKS (12 * 32)
#define W2_BLOCKS (32 * 32)

__global__ __launch_bounds__(256) void prep_kernel(
    const float* __restrict__ act,
    const float* __restrict__ gamma,
    const float* __restrict__ beta,
    const float* __restrict__ w1,
    const float* __restrict__ w2,
    __half* __restrict__ xnh, __half* __restrict__ xnl,
    __half* __restrict__ wt1h, __half* __restrict__ wt1l,
    __half* __restrict__ wt2h, __half* __restrict__ wt2l)
{
    const int b = blockIdx.x;
    if (b < LN_BLOCKS) {
        int row  = b * 8 + (threadIdx.x >> 5);
        int lane = threadIdx.x & 31;
        const float* x = act + (size_t)row * CIN;

        float v[12];
        float sum = 0.f;
#pragma unroll
        for (int i = 0; i < 12; i++) { v[i] = x[lane + i * 32]; sum += v[i]; }
#pragma unroll
        for (int o = 16; o; o >>= 1) sum += __shfl_xor_sync(0xffffffffu, sum, o);
        float mu = sum * (1.f / CIN);

        float vs = 0.f;
#pragma unroll
        for (int i = 0; i < 12; i++) { float d = v[i] - mu; vs += d * d; }
#pragma unroll
        for (int o = 16; o; o >>= 1) vs += __shfl_xor_sync(0xffffffffu, vs, o);
        float rstd = rsqrtf(vs * (1.f / CIN) + 1e-5f);

        __half* oh = xnh + (size_t)row * CIN;
        __half* ol = xnl + (size_t)row * CIN;
#pragma unroll
        for (int i = 0; i < 12; i++) {
            int c = lane + i * 32;
            float y = (v[i] - mu) * rstd * gamma[c] + beta[c];
            __half hi = __float2half_rn(y);
            oh[c] = hi;
            ol[c] = __float2half_rn(y - __half2float(hi));
        }
        return;
    }

    // transpose-split role
    __shared__ float t[32][33];
    const int tx = threadIdx.x & 31;
    const int ty = threadIdx.x >> 5;   // 0..7
    const float* W;
    __half *Th, *Tl;
    int Krows, Ncols, k0, n0;
    if (b < LN_BLOCKS + W1_BLOCKS) {
        int bb = b - LN_BLOCKS;          // 12 k-tiles x 32 n-tiles
        W = w1; Th = wt1h; Tl = wt1l; Krows = CIN; Ncols = HID;
        k0 = (bb / 32) * 32;
        n0 = (bb % 32) * 32;
    } else {
        int bb = b - LN_BLOCKS - W1_BLOCKS;  // 32 x 32
        W = w2; Th = wt2h; Tl = wt2l; Krows = HID; Ncols = HID;
        k0 = (bb / 32) * 32;
        n0 = (bb % 32) * 32;
    }

#pragma unroll
    for (int j = ty; j < 32; j += 8)
        t[j][tx] = W[(size_t)(k0 + j) * Ncols + n0 + tx];
    __syncthreads();

#pragma unroll
    for (int j = ty; j < 32; j += 8) {
        float v = t[tx][j];
        __half hi = __float2half_rn(v);
        size_t o = (size_t)(n0 + j) * Krows + k0 + tx;
        Th[o] = hi;
        Tl[o] = __float2half_rn(v - __half2float(hi));
    }
}

// ---------------- fp16x3 mma.sync m16n8k16 GEMM: 3-stage cp.async, k-tile 32 ----------------
// block tile 128(M) x 256(N) x 32(K), 16 warps (4M x 4N), warp tile 32x64
// MODE 0: C -> fp16 hi/lo split (GEMM1).  MODE 1: fused logit-partial epilogue (GEMM2).
#define SRB    176                      // bytes per smem row (11x16B, conflict-free)
#define A_ARRB (128 * SRB)              // 22528 B
#define B_ARRB (256 * SRB)              // 45056 B
#define ST_A   0
#define ST_B   A_ARRB
#define STAGEB (A_ARRB + B_ARRB)        // 67584 B
#define NSTAGE 3
#define LO_OFF 32                       // byte offset of lo half within a k16 slab

template<int K, int MODE>
__global__ __launch_bounds__(512, 1) void mma_gemm_kernel(
    const __half* __restrict__ Ah, const __half* __restrict__ Al,
    const __half* __restrict__ Bh, const __half* __restrict__ Bl,
    const float* __restrict__ bias,
    __half* __restrict__ Ch16, __half* __restrict__ Cl16,
    const float* __restrict__ w3,     // MODE 1
    float* __restrict__ gpart)        // MODE 1: [4][RTOT][20]
{
    constexpr int KT = K / 32;
    extern __shared__ char smem[];

    const int tid   = threadIdx.x;
    const int wid   = tid >> 5;
    const int lane  = tid & 31;
    const int warpM = wid & 3;          // 0..3
    const int warpN = wid >> 2;         // 0..3
    const int gr    = lane >> 2;
    const int tc    = lane & 3;

    const int m0 = blockIdx.y * 128;
    const int n0 = blockIdx.x * 256;

    const int row = tid >> 2;
    const int p0  = tid & 3;
    const int hl  = (p0 >> 1) & 1;
    const int seg = p0 & 1;
    const __half* gA  = (hl ? Al : Ah) + (size_t)(m0 + row) * K + seg * 8;
    const __half* gB0 = (hl ? Bl : Bh) + (size_t)(n0 + row) * K + seg * 8;
    const __half* gB1 = (hl ? Bl : Bh) + (size_t)(n0 + row + 128) * K + seg * 8;

    const uint32_t sbase = smem_u32(smem);
    const uint32_t dpart = (uint32_t)(hl * 32 + seg * 16);
    const uint32_t dstA  = (uint32_t)(row * SRB) + dpart;
    const uint32_t dstB0 = (uint32_t)(row * SRB) + dpart;
    const uint32_t dstB1 = (uint32_t)((row + 128) * SRB) + dpart;

    const uint32_t aLane = (uint32_t)((warpM * 32 + (lane & 15)) * SRB + (lane >> 4) * 16);
    const uint32_t bLane = (uint32_t)((warpN * 64 + (lane & 7) + ((lane >> 4) & 1) * 8) * SRB
                                      + ((lane >> 3) & 1) * 16);

    float acc[2][8][4];
#pragma unroll
    for (int i = 0; i < 2; i++)
#pragma unroll
        for (int j = 0; j < 8; j++)
#pragma unroll
            for (int q = 0; q < 4; q++) acc[i][j][q] = 0.f;

#define PREFETCH(kt_, s_) do { \
        const int _kg = (kt_) * 32; \
        const uint32_t _db = sbase + (uint32_t)(s_) * STAGEB; \
        CP16(_db + ST_A + dstA,       gA  + _kg); \
        CP16(_db + ST_A + dstA + 64,  gA  + _kg + 16); \
        CP16(_db + ST_B + dstB0,      gB0 + _kg); \
        CP16(_db + ST_B + dstB0 + 64, gB0 + _kg + 16); \
        CP16(_db + ST_B + dstB1,      gB1 + _kg); \
        CP16(_db + ST_B + dstB1 + 64, gB1 + _kg + 16); \
        CP_COMMIT(); \
    } while (0)

    PREFETCH(0, 0);
    PREFETCH(1, 1);

    int s_cur = 0;
    int s_pf  = 2;
    for (int kt = 0; kt < KT; ++kt) {
        if (kt < KT - 1) { CP_WAIT(1); }
        else             { CP_WAIT(0); }
        __syncthreads();
        if (kt + 2 < KT) {
            PREFETCH(kt + 2, s_pf);
        }

        const uint32_t stage = sbase + (uint32_t)s_cur * STAGEB;

#pragma unroll
        for (int j = 0; j < 2; j++) {
            const uint32_t aHi = stage + ST_A + aLane + j * 64;
            const uint32_t bHi = stage + ST_B + bLane + j * 64;

            uint32_t ah[2][4], al[2][4], bh[4][4], bl[4][4];
#pragma unroll
            for (int ms = 0; ms < 2; ms++) {
                ldsm4(ah[ms], aHi + ms * (16 * SRB));
                ldsm4(al[ms], aHi + ms * (16 * SRB) + LO_OFF);
            }
#pragma unroll
            for (int p = 0; p < 4; p++) {
                ldsm4(bh[p], bHi + p * (16 * SRB));
                ldsm4(bl[p], bHi + p * (16 * SRB) + LO_OFF);
            }
#pragma unroll
            for (int ms = 0; ms < 2; ms++)
#pragma unroll
                for (int p = 0; p < 4; p++) {
                    mma16(acc[ms][2 * p],     ah[ms], &bh[p][0]);
                    mma16(acc[ms][2 * p + 1], ah[ms], &bh[p][2]);
                }
#pragma unroll
            for (int ms = 0; ms < 2; ms++)
#pragma unroll
                for (int p = 0; p < 4; p++) {
                    mma16(acc[ms][2 * p],     ah[ms], &bl[p][0]);
                    mma16(acc[ms][2 * p + 1], ah[ms], &bl[p][2]);
                }
#pragma unroll
            for (int ms = 0; ms < 2; ms++)
#pragma unroll
                for (int p = 0; p < 4; p++) {
                    mma16(acc[ms][2 * p],     al[ms], &bh[p][0]);
                    mma16(acc[ms][2 * p + 1], al[ms], &bh[p][2]);
                }
        }
        s_cur = (s_cur == 2) ? 0 : s_cur + 1;
        s_pf  = (s_pf == 2) ? 0 : s_pf + 1;
    }
#undef PREFETCH

    // bias + relu in place
    const int mwb = m0 + warpM * 32;
    const int nwb = n0 + warpN * 64;
#pragma unroll
    for (int ms = 0; ms < 2; ms++)
#pragma unroll
        for (int ns = 0; ns < 8; ns++) {
            int c = nwb + ns * 8 + 2 * tc;
            float bz0 = bias[c], bz1 = bias[c + 1];
            acc[ms][ns][0] = fmaxf(acc[ms][ns][0] + bz0, 0.f);
            acc[ms][ns][1] = fmaxf(acc[ms][ns][1] + bz1, 0.f);
            acc[ms][ns][2] = fmaxf(acc[ms][ns][2] + bz0, 0.f);
            acc[ms][ns][3] = fmaxf(acc[ms][ns][3] + bz1, 0.f);
        }

    if (MODE == 0) {
#pragma unroll
        for (int ms = 0; ms < 2; ms++) {
            int r0 = mwb + ms * 16 + gr;
            int r1 = r0 + 8;
#pragma unroll
            for (int ns = 0; ns < 8; ns++) {
                int c = nwb + ns * 8 + 2 * tc;
                float v0 = acc[ms][ns][0], v1 = acc[ms][ns][1];
                float v2 = acc[ms][ns][2], v3 = acc[ms][ns][3];
                __half h0 = __float2half_rn(v0), h1 = __float2half_rn(v1);
                __half h2 = __float2half_rn(v2), h3 = __float2half_rn(v3);
                __half l0 = __float2half_rn(v0 - __half2float(h0));
                __half l1 = __float2half_rn(v1 - __half2float(h1));
                __half l2 = __float2half_rn(v2 - __half2float(h2));
                __half l3 = __float2half_rn(v3 - __half2float(h3));
                *(__half2*)(Ch16 + (size_t)r0 * HID + c) = __halves2half2(h0, h1);
                *(__half2*)(Ch16 + (size_t)r1 * HID + c) = __halves2half2(h2, h3);
                *(__half2*)(Cl16 + (size_t)r0 * HID + c) = __halves2half2(l0, l1);
                *(__half2*)(Cl16 + (size_t)r1 * HID + c) = __halves2half2(l2, l3);
            }
        }
    } else {
        // fused logit partials
        __syncthreads();
        float* w3s  = (float*)smem;                      // [256][20]
        float* slab = (float*)(smem + 256 * NRES * 4);   // [4 warpN][128][20]
        for (int i = tid; i < 256 * NRES; i += 512) {
            int col = i / NRES, c = i - col * NRES;
            w3s[i] = w3[(size_t)(n0 + col) * NRES + c];
        }
        __syncthreads();

#pragma unroll
        for (int cc = 0; cc < 5; cc++) {
            float pl[4][4];
#pragma unroll
            for (int ri = 0; ri < 4; ri++)
#pragma unroll
                for (int q = 0; q < 4; q++) pl[ri][q] = 0.f;
#pragma unroll
            for (int ns = 0; ns < 8; ns++) {
                int colb = warpN * 64 + ns * 8 + 2 * tc;
                float4 w0 = *(float4*)&w3s[colb * NRES + cc * 4];
                float4 w1 = *(float4*)&w3s[(colb + 1) * NRES + cc * 4];
#pragma unroll
                for (int ms = 0; ms < 2; ms++)
#pragma unroll
                    for (int q = 0; q < 4; q++) {
                        float v = acc[ms][ns][q];
                        const float4 wv = (q & 1) ? w1 : w0;
                        int ri = ms * 2 + (q >> 1);
                        pl[ri][0] = fmaf(v, wv.x, pl[ri][0]);
                        pl[ri][1] = fmaf(v, wv.y, pl[ri][1]);
                        pl[ri][2] = fmaf(v, wv.z, pl[ri][2]);
                        pl[ri][3] = fmaf(v, wv.w, pl[ri][3]);
                    }
            }
#pragma unroll
            for (int o = 1; o <= 2; o <<= 1)
#pragma unroll
                for (int ri = 0; ri < 4; ri++)
#pragma unroll
                    for (int q = 0; q < 4; q++)
                        pl[ri][q] += __shfl_xor_sync(0xffffffffu, pl[ri][q], o);
            if (tc == 0) {
#pragma unroll
                for (int ri = 0; ri < 4; ri++) {
                    int rloc = warpM * 32 + (ri >> 1) * 16 + (ri & 1) * 8 + gr;
                    float4 st = make_float4(pl[ri][0], pl[ri][1], pl[ri][2], pl[ri][3]);
                    *(float4*)&slab[(warpN * 128 + rloc) * NRES + cc * 4] = st;
                }
            }
        }
        __syncthreads();
        for (int i = tid; i < 128 * NRES; i += 512) {
            float s = slab[i] + slab[128 * NRES + i]
                    + slab[2 * 128 * NRES + i] + slab[3 * 128 * NRES + i];
            int rloc = i / NRES, c = i - rloc * NRES;
            gpart[((size_t)blockIdx.x * RTOT + (m0 + rloc)) * NRES + c] = s;
        }
    }
}

// ---------------- fused head + geometry: 128 thr/block, warp-staged coalesced writes ----------------
__global__ __launch_bounds__(128) void head_geom_kernel(
    const float* __restrict__ gpart,
    const float* __restrict__ b3,
    const int* __restrict__ fixed_mask,
    const int* __restrict__ seq_t,
    const float* __restrict__ angles,
    const float* __restrict__ rigids,
    const int* __restrict__ residx,
    const float* __restrict__ default_frames,
    const int* __restrict__ group_idx,
    const float* __restrict__ atom14_mask,
    const float* __restrict__ atom37_mask,
    const float* __restrict__ lit_positions,
    float* __restrict__ out_logits,
    float* __restrict__ out_seq0f,
    float* __restrict__ out_pred,
    float* __restrict__ out_final,
    float* __restrict__ out_m14,
    float* __restrict__ out_m37)
{
    __shared__ float slab[4][32 * 42];
    __shared__ int   s_sh[4][32];

    const int tid  = threadIdx.x;
    const int wid  = tid >> 5;
    const int lane = tid & 31;
    const int r    = blockIdx.x * 128 + tid;
    const int rwb  = blockIdx.x * 128 + wid * 32;

    float* sl = slab[wid];

    float lg[NRES];
#pragma unroll
    for (int c = 0; c < NRES; c++) lg[c] = b3[c];
#pragma unroll
    for (int nt = 0; nt < 4; nt++) {
        const float* p = gpart + ((size_t)nt * RTOT + r) * NRES;
#pragma unroll
        for (int c = 0; c < NRES; c += 4) {
            float4 v = *(const float4*)(p + c);
            lg[c + 0] += v.x; lg[c + 1] += v.y; lg[c + 2] += v.z; lg[c + 3] += v.w;
        }
    }
    int best = 0; float bv = -INFINITY;
#pragma unroll
    for (int c = 0; c < NRES; c++) {
        sl[lane * NRES + c] = lg[c];
        if (lg[c] > bv) { bv = lg[c]; best = c; }
    }
    int s = fixed_mask[r] ? seq_t[r] : best;
    s_sh[wid][lane] = s;
    out_seq0f[r] = (float)s;
    __syncwarp();
    for (int f = lane; f < 32 * NRES; f += 32)
        out_logits[(size_t)rwb * NRES + f] = sl[f];
    __syncwarp();

    float q0 = rigids[r * 7 + 0], q1 = rigids[r * 7 + 1];
    float q2 = rigids[r * 7 + 2], q3 = rigids[r * 7 + 3];
    float tb0 = rigids[r * 7 + 4], tb1 = rigids[r * 7 + 5], tb2 = rigids[r * 7 + 6];
    float inv = rsqrtf(q0 * q0 + q1 * q1 + q2 * q2 + q3 * q3 + 1e-8f);
    float w = q0 * inv, x = q1 * inv, y = q2 * inv, z = q3 * inv;
    float rb[9];
    rb[0] = 1.f - 2.f * (y * y + z * z); rb[1] = 2.f * (x * y - w * z); rb[2] = 2.f * (x * z + w * y);
    rb[3] = 2.f * (x * y + w * z); rb[4] = 1.f - 2.f * (x * x + z * z); rb[5] = 2.f * (y * z - w * x);
    rb[6] = 2.f * (x * z - w * y); rb[7] = 2.f * (y * z + w * x); rb[8] = 1.f - 2.f * (x * x + y * y);

    float G[8][12];
    float chain_r[9], chain_t[3];

    for (int g = 0; g < 8; g++) {
        const float* df = default_frames + ((size_t)s * 8 + g) * 16;
        float dr[9], dt[3];
#pragma unroll
        for (int i = 0; i < 3; i++) {
            dr[i * 3 + 0] = df[i * 4 + 0];
            dr[i * 3 + 1] = df[i * 4 + 1];
            dr[i * 3 + 2] = df[i * 4 + 2];
            dt[i] = df[i * 4 + 3];
        }
        float sn, cs;
        if (g == 0) { sn = 0.f; cs = 1.f; }
        else { sn = angles[r * 14 + (g - 1) * 2 + 0]; cs = angles[r * 14 + (g - 1) * 2 + 1]; }

        float fr[9], ft[3];
#pragma unroll
        for (int i = 0; i < 3; i++) {
            fr[i * 3 + 0] = dr[i * 3 + 0];
            fr[i * 3 + 1] = dr[i * 3 + 1] * cs + dr[i * 3 + 2] * sn;
            fr[i * 3 + 2] = -dr[i * 3 + 1] * sn + dr[i * 3 + 2] * cs;
            ft[i] = dt[i];
        }

        float fo[9], to[3];
        if (g <= 4) {
#pragma unroll
            for (int i = 0; i < 9; i++) fo[i] = fr[i];
#pragma unroll
            for (int i = 0; i < 3; i++) to[i] = ft[i];
            if (g == 4) {
#pragma unroll
                for (int i = 0; i < 9; i++) chain_r[i] = fr[i];
#pragma unroll
                for (int i = 0; i < 3; i++) chain_t[i] = ft[i];
            }
        } else {
            float nr[9], nt[3];
#pragma unroll
            for (int i = 0; i < 3; i++) {
#pragma unroll
                for (int j = 0; j < 3; j++) {
                    nr[i * 3 + j] = chain_r[i * 3 + 0] * fr[0 * 3 + j]
                                  + chain_r[i * 3 + 1] * fr[1 * 3 + j]
                                  + chain_r[i * 3 + 2] * fr[2 * 3 + j];
                }
                nt[i] = chain_r[i * 3 + 0] * ft[0] + chain_r[i * 3 + 1] * ft[1]
                      + chain_r[i * 3 + 2] * ft[2] + chain_t[i];
            }
#pragma unroll
            for (int i = 0; i < 9; i++) { chain_r[i] = nr[i]; fo[i] = nr[i]; }
#pragma unroll
            for (int i = 0; i < 3; i++) { chain_t[i] = nt[i]; to[i] = nt[i]; }
        }

#pragma unroll
        for (int i = 0; i < 3; i++) {
#pragma unroll
            for (int j = 0; j < 3; j++) {
                G[g][i * 3 + j] = rb[i * 3 + 0] * fo[0 * 3 + j]
                                + rb[i * 3 + 1] * fo[1 * 3 + j]
                                + rb[i * 3 + 2] * fo[2 * 3 + j];
            }
        }
        G[g][9]  = rb[0] * to[0] + rb[1] * to[1] + rb[2] * to[2] + tb0;
        G[g][10] = rb[3] * to[0] + rb[4] * to[1] + rb[5] * to[2] + tb1;
        G[g][11] = rb[6] * to[0] + rb[7] * to[1] + rb[8] * to[2] + tb2;
    }

#pragma unroll
    for (int a = 0; a < 14; a++) {
        int gi = group_idx[s * 14 + a];
        const float* Gp = G[gi];
        float lx = lit_positions[((size_t)s * 14 + a) * 3 + 0];
        float ly = lit_positions[((size_t)s * 14 + a) * 3 + 1];
        float lz = lit_positions[((size_t)s * 14 + a) * 3 + 2];
        float m = atom14_mask[s * 14 + a];
        sl[lane * 42 + a * 3 + 0] = (Gp[0] * lx + Gp[1] * ly + Gp[2] * lz + Gp[9])  * m;
        sl[lane * 42 + a * 3 + 1] = (Gp[3] * lx + Gp[4] * ly + Gp[5] * lz + Gp[10]) * m;
        sl[lane * 42 + a * 3 + 2] = (Gp[6] * lx + Gp[7] * ly + Gp[8] * lz + Gp[11]) * m;
    }
    __syncwarp();

    for (int f = lane; f < 32 * 42; f += 32)
        out_pred[(size_t)rwb * 42 + f] = sl[f];

    for (int f = lane; f < 32 * 14; f += 32) {
        int rr = f / 14, a = f - rr * 14;
        out_m14[(size_t)rwb * 14 + f] = atom14_mask[s_sh[wid][rr] * 14 + a];
    }

    for (int f = lane; f < 32 * 37; f += 32) {
        int rr = f / 37, j = f - rr * 37;
        out_m37[(size_t)rwb * 37 + f] = atom37_mask[s_sh[wid][rr] * 37 + j];
    }

    for (int f = lane; f < 32 * 111; f += 32) {
        int rr = f / 111;
        int rem = f - rr * 111;
        int j = rem / 3, q = rem - j * 3;
        int a = residx[(size_t)(rwb + rr) * 37 + j];
        out_final[(size_t)rwb * 111 + f] = sl[rr * 42 + a * 3 + q];
    }
}

// ---------------- launcher ----------------
extern "C" void kernel_launch(void* const* d_in, const int* in_sizes, int n_in,
                              void* d_out, int out_size)
{
    const float* act        = (const float*)d_in[0];
    const float* angles     = (const float*)d_in[1];
    const float* rigids     = (const float*)d_in[2];
    const int*   fixed_mask = (const int*)d_in[3];
    const int*   seq_t      = (const int*)d_in[4];
    const int*   residx     = (const int*)d_in[5];
    const float* ln_g       = (const float*)d_in[6];
    const float* ln_b       = (const float*)d_in[7];
    const float* w1         = (const float*)d_in[8];
    const float* b1         = (const float*)d_in[9];
    const float* w2         = (const float*)d_in[10];
    const float* b2         = (const float*)d_in[11];
    const float* w3         = (const float*)d_in[12];
    const float* b3         = (const float*)d_in[13];
    const float* dframes    = (const float*)d_in[14];
    const int*   group_idx  = (const int*)d_in[15];
    const float* a14_mask   = (const float*)d_in[16];
    const float* a37_mask   = (const float*)d_in[17];
    const float* lit        = (const float*)d_in[18];

    float* out = (float*)d_out;
    float* out_logits = out + OFF_LOGITS;
    float* out_seq0   = out + OFF_SEQ0;
    float* out_pred   = out + OFF_PRED;
    float* out_final  = out + OFF_FINAL;
    float* out_m14    = out + OFF_M14;
    float* out_m37    = out + OFF_M37;

    __half *xnh, *xnl, *h1h, *h1l, *wt1h, *wt1l, *wt2h, *wt2l;
    float *gpart;
    cudaGetSymbolAddress((void**)&xnh, g_xn_hi);
    cudaGetSymbolAddress((void**)&xnl, g_xn_lo);
    cudaGetSymbolAddress((void**)&h1h, g_h1_hi);
    cudaGetSymbolAddress((void**)&h1l, g_h1_lo);
    cudaGetSymbolAddress((void**)&wt1h, g_wt1_hi);
    cudaGetSymbolAddress((void**)&wt1l, g_wt1_lo);
    cudaGetSymbolAddress((void**)&wt2h, g_wt2_hi);
    cudaGetSymbolAddress((void**)&wt2l, g_wt2_lo);
    cudaGetSymbolAddress((void**)&gpart, g_part);

    const int GEMM_SMEM = NSTAGE * STAGEB;   // 202752 B -> 1 CTA, 16 warps/SM
    cudaFuncSetAttribute(mma_gemm_kernel<CIN, 0>,
                         cudaFuncAttributeMaxDynamicSharedMemorySize, GEMM_SMEM);
    cudaFuncSetAttribute(mma_gemm_kernel<HID, 1>,
                         cudaFuncAttributeMaxDynamicSharedMemorySize, GEMM_SMEM);

    // 1. combined prep: LN split + both weight transpose-splits (one launch)
    prep_kernel<<<LN_BLOCKS + W1_BLOCKS + W2_BLOCKS, 256>>>(
        act, ln_g, ln_b, w1, w2, xnh, xnl, wt1h, wt1l, wt2h, wt2l);

    // 2. GEMM1: relu(xn @ w1 + b1) -> h1 (fp16 split)
    {
        dim3 grid(HID / 256, RTOT / 128);
        mma_gemm_kernel<CIN, 0><<<grid, 512, GEMM_SMEM>>>(
            xnh, xnl, wt1h, wt1l, b1, h1h, h1l, nullptr, nullptr);
    }
    // 3. GEMM2 fused: relu(h1 @ w2 + b2) @ w3-slice -> logit partials
    {
        dim3 grid(HID / 256, RTOT / 128);
        mma_gemm_kernel<HID, 1><<<grid, 512, GEMM_SMEM>>>(
            h1h, h1l, wt2h, wt2l, b2, nullptr, nullptr, w3, gpart);
    }
    // 4. fused head + geometry (coalesced staged writes)
    head_geom_kernel<<<RTOT / 128, 128>>>(gpart, b3, fixed_mask, seq_t,
                                          angles, rigids, residx, dframes, group_idx,
                                          a14_mask, a37_mask, lit,
                                          out_logits, out_seq0,
                                          out_pred, out_final, out_m14, out_m37);
}